// round 7
// baseline (speedup 1.0000x reference)
#include <cuda_runtime.h>
#include <cuda_fp16.h>
#include <cstdint>
#include <math.h>

// HierarchicalSoftmax, levels [16,256,4096], D=2048, B=4096.
// fp16 mma.sync (m16n8k16, fp32 accum) + cp.async multistage + fused
// group-of-16 log-softmax.
//   cvt (1 launch): x,W2,W1,W0 -> fp16 scratch
//   K1 (level0 folded): lp0 -> out[:,0:16], lp1 -> out[:,16:272]
//   K2 (256x128 tiles): lp2 -> out[:,272:4368] and out[B*OW:]

namespace {

constexpr int D_  = 2048;
constexpr int BK  = 64;          // K per stage (one 128B smem row of fp16)
constexpr int NK  = D_ / BK;     // 32
constexpr int OW  = 4368;

__device__ __half g_xh[4096 * 2048];
__device__ __half g_w2h[4096 * 2048];
__device__ __half g_w1h[272 * 2048];     // W1 (256 rows) then W0 (16 rows)

__device__ __forceinline__ uint32_t smem_u32(const void* p) {
    return (uint32_t)__cvta_generic_to_shared(p);
}
__device__ __forceinline__ void cp16(uint32_t dst, const void* src) {
    asm volatile("cp.async.cg.shared.global [%0], [%1], 16;" :: "r"(dst), "l"(src) : "memory");
}
__device__ __forceinline__ void cp_commit() {
    asm volatile("cp.async.commit_group;" ::: "memory");
}
template <int N>
__device__ __forceinline__ void cp_wait() {
    asm volatile("cp.async.wait_group %0;" :: "n"(N) : "memory");
}
__device__ __forceinline__ void ldsm4(uint32_t& r0, uint32_t& r1, uint32_t& r2, uint32_t& r3,
                                      uint32_t a) {
    asm volatile("ldmatrix.sync.aligned.m8n8.x4.shared.b16 {%0,%1,%2,%3}, [%4];"
                 : "=r"(r0), "=r"(r1), "=r"(r2), "=r"(r3) : "r"(a));
}
__device__ __forceinline__ void mma_f16(float* c, const uint32_t* a, const uint32_t* b) {
    asm volatile("mma.sync.aligned.m16n8k16.row.col.f32.f16.f16.f32 "
                 "{%0,%1,%2,%3}, {%4,%5,%6,%7}, {%8,%9}, {%0,%1,%2,%3};"
                 : "+f"(c[0]), "+f"(c[1]), "+f"(c[2]), "+f"(c[3])
                 : "r"(a[0]), "r"(a[1]), "r"(a[2]), "r"(a[3]), "r"(b[0]), "r"(b[1]));
}

__device__ __forceinline__ float lse16(const float* v) {
    float m = v[0];
#pragma unroll
    for (int j = 1; j < 16; j++) m = fmaxf(m, v[j]);
    float s = 0.f;
#pragma unroll
    for (int j = 0; j < 16; j++) s += __expf(v[j] - m);
    return m + __logf(s);
}

// ---------------------------------------------------------------------------
// fused fp32 -> fp16 convert of all four tensors (one launch)
// ---------------------------------------------------------------------------
__global__ __launch_bounds__(256)
void cvt_all(const float* __restrict__ x, const float* __restrict__ W2,
             const float* __restrict__ W1, const float* __restrict__ W0, int B)
{
    const int nx  = B * D_ / 4;            // float4 counts
    const int nw2 = 4096 * D_ / 4;
    const int nw1 = 256 * D_ / 4;
    const int nw0 = 16 * D_ / 4;
    const int total = nx + nw2 + nw1 + nw0;

    for (int i = blockIdx.x * blockDim.x + threadIdx.x; i < total;
         i += gridDim.x * blockDim.x) {
        const float* src;
        __half* dst;
        int j = i;
        if (j < nx)                { src = x;  dst = g_xh; }
        else if ((j -= nx) < nw2)  { src = W2; dst = g_w2h; }
        else if ((j -= nw2) < nw1) { src = W1; dst = g_w1h; }
        else { j -= nw1;             src = W0; dst = g_w1h + 256 * D_; }
        float4 v = reinterpret_cast<const float4*>(src)[j];
        __half2 h0 = __floats2half2_rn(v.x, v.y);
        __half2 h1 = __floats2half2_rn(v.z, v.w);
        reinterpret_cast<__half2*>(dst)[2 * j]     = h0;
        reinterpret_cast<__half2*>(dst)[2 * j + 1] = h1;
    }
}

// ---------------------------------------------------------------------------
// fp16 mma GEMM + fused hierarchical-softmax epilogue.
// LEVEL==1: BROWS = BN + 16 (W0 rows appended in g_w1h); computes lp0 in-CTA.
// ---------------------------------------------------------------------------
template <int BM, int BN, int BROWS, int NTH, int WGM, int WGN, int NSTG,
          int MAXB, int LEVEL>
__global__ __launch_bounds__(NTH, MAXB)
void hs_mma(const __half* __restrict__ xh, const __half* __restrict__ Wh,
            const float* __restrict__ bias, const float* __restrict__ b0,
            float* __restrict__ out, int B)
{
    constexpr int WM = BM / WGM;
    constexpr int WN = BN / WGN;
    constexpr int MT = WM / 16;
    constexpr int NT = WN / 8;
    constexpr int A_BYTES = BM * 128;
    constexpr int B_BYTES = BROWS * 128;
    constexpr int STAGE   = A_BYTES + B_BYTES;
    constexpr int ACH = BM * 8 / NTH;
    constexpr int BCH = BROWS * 8 / NTH;
    constexpr int EST = BROWS + 4;
    constexpr bool FOLD = (LEVEL == 1);

    extern __shared__ char smc[];
    __shared__ float lse0v[BM > 32 ? BM : 32];
    const uint32_t sb = smem_u32(smc);

    const int tid  = threadIdx.x;
    const int w    = tid >> 5;
    const int lane = tid & 31;
    const int row0 = blockIdx.y * BM;
    const int n0   = blockIdx.x * BN;

    const int wm = w % WGM;
    const int wn = w / WGM;

    const __half* xblk = xh + (size_t)row0 * D_;

    float c[MT][NT][4];
#pragma unroll
    for (int i = 0; i < MT; i++)
#pragma unroll
        for (int j = 0; j < NT; j++)
#pragma unroll
            for (int k = 0; k < 4; k++) c[i][j][k] = 0.f;

    float cx[MT][4];
    if (FOLD) {
#pragma unroll
        for (int i = 0; i < MT; i++)
#pragma unroll
            for (int k = 0; k < 4; k++) cx[i][k] = 0.f;
    }

    auto load_tile = [&](int s, int t) {
        const int k0 = t * BK;
        const uint32_t as = sb + s * STAGE;
        const uint32_t bs = as + A_BYTES;
#pragma unroll
        for (int i = 0; i < ACH; i++) {
            int cidx = tid + i * NTH;
            int r = cidx >> 3, kq = cidx & 7;
            cp16(as + r * 128 + ((kq ^ (r & 7)) << 4),
                 xblk + (size_t)r * D_ + k0 + kq * 8);
        }
#pragma unroll
        for (int i = 0; i < BCH; i++) {
            int cidx = tid + i * NTH;
            int r = cidx >> 3, kq = cidx & 7;
            const int srow = (!FOLD || r < BN) ? (n0 + r) : (256 + (r - BN));
            cp16(bs + r * 128 + ((kq ^ (r & 7)) << 4),
                 Wh + (size_t)srow * D_ + k0 + kq * 8);
        }
    };

    const int sel = lane >> 3, lr = lane & 7;
    const int a_row_off = ((sel & 1) << 3) + lr;
    const int a_c16_off = (sel >> 1);
    const int b_row_off = ((sel >> 1) << 3) + lr;
    const int b_c16_off = (sel & 1);

#pragma unroll
    for (int i = 0; i < NSTG - 1; i++) { load_tile(i, i); cp_commit(); }

    for (int t = 0; t < NK; t++) {
        cp_wait<NSTG - 2>();
        __syncthreads();

        // issue next stage's loads first: overlaps with this iteration's MMAs.
        // Safe: stage (t+NSTG-1)%NSTG == (t-1)%NSTG was consumed in iter t-1,
        // and the barrier above orders all of iter t-1 before these writes.
        if (t + NSTG - 1 < NK) load_tile((t + NSTG - 1) % NSTG, t + NSTG - 1);
        cp_commit();

        const int s = t % NSTG;
        const uint32_t as = sb + s * STAGE;
        const uint32_t bs = as + A_BYTES;

#pragma unroll
        for (int ks = 0; ks < BK / 16; ks++) {
            uint32_t af[MT][4];
#pragma unroll
            for (int mt = 0; mt < MT; mt++) {
                int row = wm * WM + mt * 16 + a_row_off;
                int c16 = ks * 2 + a_c16_off;
                ldsm4(af[mt][0], af[mt][1], af[mt][2], af[mt][3],
                      as + row * 128 + (((c16 ^ lr) & 7) << 4));
            }
            uint32_t bf[NT][2];
#pragma unroll
            for (int np = 0; np < NT / 2; np++) {
                int row = wn * WN + np * 16 + b_row_off;
                int c16 = ks * 2 + b_c16_off;
                uint32_t r0, r1, r2, r3;
                ldsm4(r0, r1, r2, r3, bs + row * 128 + (((c16 ^ lr) & 7) << 4));
                bf[np * 2][0] = r0; bf[np * 2][1] = r1;
                bf[np * 2 + 1][0] = r2; bf[np * 2 + 1][1] = r3;
            }
#pragma unroll
            for (int mt = 0; mt < MT; mt++)
#pragma unroll
                for (int nt = 0; nt < NT; nt++)
                    mma_f16(c[mt][nt], af[mt], bf[nt]);

            if (FOLD && w < 2) {
                int row = BN + b_row_off;
                int c16 = ks * 2 + b_c16_off;
                uint32_t r0, r1, r2, r3;
                ldsm4(r0, r1, r2, r3, bs + row * 128 + (((c16 ^ lr) & 7) << 4));
                uint32_t bfx[2];
                if (w == 0) { bfx[0] = r0; bfx[1] = r1; }
                else        { bfx[0] = r2; bfx[1] = r3; }
#pragma unroll
                for (int mt = 0; mt < MT; mt++)
                    mma_f16(cx[mt], af[mt], bfx);
            }
        }
    }

    cp_wait<0>();
    __syncthreads();

    // ---- frags (+bias) -> smem ----
    float* S = (float*)smc;   // [BM][EST]
    const int g = lane >> 2, tq = lane & 3;
#pragma unroll
    for (int nt = 0; nt < NT; nt++) {
        const int col = wn * WN + nt * 8 + tq * 2;
        const float bb0 = __ldg(&bias[n0 + col]);
        const float bb1 = __ldg(&bias[n0 + col + 1]);
#pragma unroll
        for (int mt = 0; mt < MT; mt++) {
            const int row = wm * WM + mt * 16 + g;
            S[row * EST + col]           = c[mt][nt][0] + bb0;
            S[row * EST + col + 1]       = c[mt][nt][1] + bb1;
            S[(row + 8) * EST + col]     = c[mt][nt][2] + bb0;
            S[(row + 8) * EST + col + 1] = c[mt][nt][3] + bb1;
        }
    }
    if (FOLD && w < 2) {
        const int cl = w * 8 + tq * 2;
        const float bb0 = __ldg(&b0[cl]);
        const float bb1 = __ldg(&b0[cl + 1]);
#pragma unroll
        for (int mt = 0; mt < MT; mt++) {
            const int row = wm * WM + mt * 16 + g;
            S[row * EST + BN + cl]           = cx[mt][0] + bb0;
            S[row * EST + BN + cl + 1]       = cx[mt][1] + bb1;
            S[(row + 8) * EST + BN + cl]     = cx[mt][2] + bb0;
            S[(row + 8) * EST + BN + cl + 1] = cx[mt][3] + bb1;
        }
    }
    __syncthreads();

    // ---- level-0 lse + lp0 write (fold only) ----
    if (FOLD) {
        if (tid < BM) lse0v[tid] = lse16(S + tid * EST + BN);
        __syncthreads();
        if (blockIdx.x == 0 && tid < BM) {
            const float l0 = lse0v[tid];
            const float* p = S + tid * EST + BN;
            float* o = out + (size_t)(row0 + tid) * OW;
#pragma unroll
            for (int cc = 0; cc < 4; cc++) {
                float4 v;
                v.x = p[cc * 4 + 0] - l0; v.y = p[cc * 4 + 1] - l0;
                v.z = p[cc * 4 + 2] - l0; v.w = p[cc * 4 + 3] - l0;
                reinterpret_cast<float4*>(o)[cc] = v;
            }
        }
    }

    // ---- group-of-16 log-softmax (+parent chain), in place ----
    constexpr int GROUPS = BN / 16;
    for (int task = tid; task < BM * GROUPS; task += NTH) {
        const int rr = task / GROUPS;
        const int gg = task % GROUPS;
        float* p = S + rr * EST + gg * 16;
        const float lse = lse16(p);
        const int grow = row0 + rr;
        const int gc   = n0 + gg * 16;
        float pl;
        if (FOLD) {
            pl = S[rr * EST + BN + (gc >> 4)] - lse0v[rr];
        } else {
            pl = out[(size_t)grow * OW + 16 + (gc >> 4)];
        }
        const float adj = pl - lse;
#pragma unroll
        for (int j = 0; j < 16; j++) p[j] += adj;
    }
    __syncthreads();

    // ---- coalesced store-out ----
    constexpr int F4 = BN / 4;
    for (int idx = tid; idx < BM * F4; idx += NTH) {
        const int rr = idx / F4, c4 = idx % F4;
        float4 val = *reinterpret_cast<const float4*>(S + rr * EST + c4 * 4);
        const int gr = row0 + rr;
        const int gc = n0 + c4 * 4;
        if (LEVEL == 1)
            *reinterpret_cast<float4*>(out + (size_t)gr * OW + 16 + gc) = val;
        if (LEVEL == 2) {
            *reinterpret_cast<float4*>(out + (size_t)gr * OW + 272 + gc) = val;
            *reinterpret_cast<float4*>(out + (size_t)B * OW + (size_t)gr * 4096 + gc) = val;
        }
    }
}

} // namespace

extern "C" void kernel_launch(void* const* d_in, const int* in_sizes, int n_in,
                              void* d_out, int out_size)
{
    const float* x  = (const float*)d_in[0];
    const float* W0 = (const float*)d_in[1];
    const float* b0 = (const float*)d_in[2];
    const float* W1 = (const float*)d_in[3];
    const float* b1 = (const float*)d_in[4];
    const float* W2 = (const float*)d_in[5];
    const float* b2 = (const float*)d_in[6];
    float* out = (float*)d_out;
    const int B = in_sizes[0] / D_;   // 4096

    __half *xh, *w2h, *w1h;
    cudaGetSymbolAddress((void**)&xh,  g_xh);
    cudaGetSymbolAddress((void**)&w2h, g_w2h);
    cudaGetSymbolAddress((void**)&w1h, g_w1h);

    cvt_all<<<2048, 256>>>(x, W2, W1, W0, B);

    // K1: BM=32, BN=128 (+16 folded W0 rows), 4 warps, NS=3
    constexpr int SM_K1  = 3 * (32 * 128 + 144 * 128);
    constexpr int EPI_K1 = 32 * (144 + 4) * 4;
    constexpr int DYN_K1 = (SM_K1 > EPI_K1) ? SM_K1 : EPI_K1;
    // K2: BM=256, BN=128, 8 warps (warp tile 64x64), NS=3 -> 147456 B
    constexpr int SM_K2  = 3 * (256 * 128 + 128 * 128);    // 147456
    constexpr int EPI_K2 = 256 * (128 + 4) * 4;            // 135168
    constexpr int DYN_K2 = (SM_K2 > EPI_K2) ? SM_K2 : EPI_K2;

    cudaFuncSetAttribute((const void*)hs_mma<32, 128, 144, 128, 1, 4, 3, 2, 1>,
                         cudaFuncAttributeMaxDynamicSharedMemorySize, DYN_K1);
    cudaFuncSetAttribute((const void*)hs_mma<256, 128, 128, 256, 4, 2, 3, 1, 2>,
                         cudaFuncAttributeMaxDynamicSharedMemorySize, DYN_K2);

    hs_mma<32, 128, 144, 128, 1, 4, 3, 2, 1>
        <<<dim3(2, B / 32), 128, DYN_K1>>>(xh, w1h, b1, b0, out, B);
    hs_mma<256, 128, 128, 256, 4, 2, 3, 1, 2>
        <<<dim3(32, B / 256), 256, DYN_K2>>>(xh, w2h, b2, nullptr, out, B);
}

// round 9
// speedup vs baseline: 1.1891x; 1.1891x over previous
#include <cuda_runtime.h>
#include <cuda_fp16.h>
#include <cstdint>
#include <math.h>

// HierarchicalSoftmax, levels [16,256,4096], D=2048, B=4096.
// fp16 mma.sync (m16n8k16, fp32 accum) + cp.async multistage + fused
// group-of-16 log-softmax.
//   cvt (1 launch): x,W2,W1,W0 -> fp16 scratch
//   K1 (level0 folded): lp0 -> out[:,0:16], lp1 -> out[:,16:272]
//   K2 (128x128 tiles, 2 CTAs/SM): lp2 -> out[:,272:4368] and out[B*OW:]

namespace {

constexpr int D_  = 2048;
constexpr int BK  = 64;          // K per stage (one 128B smem row of fp16)
constexpr int NK  = D_ / BK;     // 32
constexpr int OW  = 4368;

__device__ __half g_xh[4096 * 2048];
__device__ __half g_w2h[4096 * 2048];
__device__ __half g_w1h[272 * 2048];     // W1 (256 rows) then W0 (16 rows)

__device__ __forceinline__ uint32_t smem_u32(const void* p) {
    return (uint32_t)__cvta_generic_to_shared(p);
}
__device__ __forceinline__ void cp16(uint32_t dst, const void* src) {
    asm volatile("cp.async.cg.shared.global [%0], [%1], 16;" :: "r"(dst), "l"(src) : "memory");
}
__device__ __forceinline__ void cp_commit() {
    asm volatile("cp.async.commit_group;" ::: "memory");
}
template <int N>
__device__ __forceinline__ void cp_wait() {
    asm volatile("cp.async.wait_group %0;" :: "n"(N) : "memory");
}
__device__ __forceinline__ void ldsm4(uint32_t& r0, uint32_t& r1, uint32_t& r2, uint32_t& r3,
                                      uint32_t a) {
    asm volatile("ldmatrix.sync.aligned.m8n8.x4.shared.b16 {%0,%1,%2,%3}, [%4];"
                 : "=r"(r0), "=r"(r1), "=r"(r2), "=r"(r3) : "r"(a));
}
__device__ __forceinline__ void mma_f16(float* c, const uint32_t* a, const uint32_t* b) {
    asm volatile("mma.sync.aligned.m16n8k16.row.col.f32.f16.f16.f32 "
                 "{%0,%1,%2,%3}, {%4,%5,%6,%7}, {%8,%9}, {%0,%1,%2,%3};"
                 : "+f"(c[0]), "+f"(c[1]), "+f"(c[2]), "+f"(c[3])
                 : "r"(a[0]), "r"(a[1]), "r"(a[2]), "r"(a[3]), "r"(b[0]), "r"(b[1]));
}

__device__ __forceinline__ float lse16(const float* v) {
    float m = v[0];
#pragma unroll
    for (int j = 1; j < 16; j++) m = fmaxf(m, v[j]);
    float s = 0.f;
#pragma unroll
    for (int j = 0; j < 16; j++) s += __expf(v[j] - m);
    return m + __logf(s);
}

// ---------------------------------------------------------------------------
// fused fp32 -> fp16 convert of all four tensors (one launch)
// ---------------------------------------------------------------------------
__global__ __launch_bounds__(256)
void cvt_all(const float* __restrict__ x, const float* __restrict__ W2,
             const float* __restrict__ W1, const float* __restrict__ W0, int B)
{
    const int nx  = B * D_ / 4;            // float4 counts
    const int nw2 = 4096 * D_ / 4;
    const int nw1 = 256 * D_ / 4;
    const int nw0 = 16 * D_ / 4;
    const int total = nx + nw2 + nw1 + nw0;

    for (int i = blockIdx.x * blockDim.x + threadIdx.x; i < total;
         i += gridDim.x * blockDim.x) {
        const float* src;
        __half* dst;
        int j = i;
        if (j < nx)                { src = x;  dst = g_xh; }
        else if ((j -= nx) < nw2)  { src = W2; dst = g_w2h; }
        else if ((j -= nw2) < nw1) { src = W1; dst = g_w1h; }
        else { j -= nw1;             src = W0; dst = g_w1h + 256 * D_; }
        float4 v = reinterpret_cast<const float4*>(src)[j];
        __half2 h0 = __floats2half2_rn(v.x, v.y);
        __half2 h1 = __floats2half2_rn(v.z, v.w);
        reinterpret_cast<__half2*>(dst)[2 * j]     = h0;
        reinterpret_cast<__half2*>(dst)[2 * j + 1] = h1;
    }
}

// ---------------------------------------------------------------------------
// fp16 mma GEMM + fused hierarchical-softmax epilogue.
// LEVEL==1: BROWS = BN + 16 (W0 rows appended in g_w1h); computes lp0 in-CTA.
// ---------------------------------------------------------------------------
template <int BM, int BN, int BROWS, int NTH, int WGM, int WGN, int NSTG,
          int MAXB, int LEVEL>
__global__ __launch_bounds__(NTH, MAXB)
void hs_mma(const __half* __restrict__ xh, const __half* __restrict__ Wh,
            const float* __restrict__ bias, const float* __restrict__ b0,
            float* __restrict__ out, int B)
{
    constexpr int WM = BM / WGM;
    constexpr int WN = BN / WGN;
    constexpr int MT = WM / 16;
    constexpr int NT = WN / 8;
    constexpr int A_BYTES = BM * 128;      // BM rows x 128B (64 fp16)
    constexpr int B_BYTES = BROWS * 128;
    constexpr int STAGE   = A_BYTES + B_BYTES;
    constexpr int ACH = BM * 8 / NTH;
    constexpr int BCH = BROWS * 8 / NTH;
    constexpr int EST = BROWS + 4;
    constexpr bool FOLD = (LEVEL == 1);

    extern __shared__ char smc[];
    __shared__ float lse0v[BM > 32 ? BM : 32];
    const uint32_t sb = smem_u32(smc);

    const int tid  = threadIdx.x;
    const int w    = tid >> 5;
    const int lane = tid & 31;
    const int row0 = blockIdx.y * BM;
    const int n0   = blockIdx.x * BN;

    const int wm = w % WGM;
    const int wn = w / WGM;

    const __half* xblk = xh + (size_t)row0 * D_;

    float c[MT][NT][4];
#pragma unroll
    for (int i = 0; i < MT; i++)
#pragma unroll
        for (int j = 0; j < NT; j++)
#pragma unroll
            for (int k = 0; k < 4; k++) c[i][j][k] = 0.f;

    float cx[MT][4];
    if (FOLD) {
#pragma unroll
        for (int i = 0; i < MT; i++)
#pragma unroll
            for (int k = 0; k < 4; k++) cx[i][k] = 0.f;
    }

    auto load_tile = [&](int s, int t) {
        const int k0 = t * BK;
        const uint32_t as = sb + s * STAGE;
        const uint32_t bs = as + A_BYTES;
#pragma unroll
        for (int i = 0; i < ACH; i++) {
            int cidx = tid + i * NTH;
            int r = cidx >> 3, kq = cidx & 7;
            cp16(as + r * 128 + ((kq ^ (r & 7)) << 4),
                 xblk + (size_t)r * D_ + k0 + kq * 8);
        }
#pragma unroll
        for (int i = 0; i < BCH; i++) {
            int cidx = tid + i * NTH;
            int r = cidx >> 3, kq = cidx & 7;
            const int srow = (!FOLD || r < BN) ? (n0 + r) : (256 + (r - BN));
            cp16(bs + r * 128 + ((kq ^ (r & 7)) << 4),
                 Wh + (size_t)srow * D_ + k0 + kq * 8);
        }
    };

    const int sel = lane >> 3, lr = lane & 7;
    const int a_row_off = ((sel & 1) << 3) + lr;
    const int a_c16_off = (sel >> 1);              // + ks*2
    const int b_row_off = ((sel >> 1) << 3) + lr;
    const int b_c16_off = (sel & 1);               // + ks*2

#pragma unroll
    for (int i = 0; i < NSTG - 1; i++) { load_tile(i, i); cp_commit(); }

    for (int t = 0; t < NK; t++) {
        cp_wait<NSTG - 2>();
        __syncthreads();

        const int s = t % NSTG;
        const uint32_t as = sb + s * STAGE;
        const uint32_t bs = as + A_BYTES;

#pragma unroll
        for (int ks = 0; ks < BK / 16; ks++) {     // 4 k16 steps per 128B row
            uint32_t af[MT][4];
#pragma unroll
            for (int mt = 0; mt < MT; mt++) {
                int row = wm * WM + mt * 16 + a_row_off;
                int c16 = ks * 2 + a_c16_off;
                ldsm4(af[mt][0], af[mt][1], af[mt][2], af[mt][3],
                      as + row * 128 + (((c16 ^ lr) & 7) << 4));
            }
            uint32_t bf[NT][2];
#pragma unroll
            for (int np = 0; np < NT / 2; np++) {
                int row = wn * WN + np * 16 + b_row_off;
                int c16 = ks * 2 + b_c16_off;
                uint32_t r0, r1, r2, r3;
                ldsm4(r0, r1, r2, r3, bs + row * 128 + (((c16 ^ lr) & 7) << 4));
                bf[np * 2][0] = r0; bf[np * 2][1] = r1;
                bf[np * 2 + 1][0] = r2; bf[np * 2 + 1][1] = r3;
            }
#pragma unroll
            for (int mt = 0; mt < MT; mt++)
#pragma unroll
                for (int nt = 0; nt < NT; nt++)
                    mma_f16(c[mt][nt], af[mt], bf[nt]);

            if (FOLD && w < 2) {
                int row = BN + b_row_off;
                int c16 = ks * 2 + b_c16_off;
                uint32_t r0, r1, r2, r3;
                ldsm4(r0, r1, r2, r3, bs + row * 128 + (((c16 ^ lr) & 7) << 4));
                uint32_t bfx[2];
                if (w == 0) { bfx[0] = r0; bfx[1] = r1; }
                else        { bfx[0] = r2; bfx[1] = r3; }
#pragma unroll
                for (int mt = 0; mt < MT; mt++)
                    mma_f16(cx[mt], af[mt], bfx);
            }
        }

        __syncthreads();
        if (t + NSTG - 1 < NK) load_tile((t + NSTG - 1) % NSTG, t + NSTG - 1);
        cp_commit();
    }

    cp_wait<0>();
    __syncthreads();

    // ---- frags (+bias) -> smem ----
    float* S = (float*)smc;   // [BM][EST]
    const int g = lane >> 2, tq = lane & 3;
#pragma unroll
    for (int nt = 0; nt < NT; nt++) {
        const int col = wn * WN + nt * 8 + tq * 2;
        const float bb0 = __ldg(&bias[n0 + col]);
        const float bb1 = __ldg(&bias[n0 + col + 1]);
#pragma unroll
        for (int mt = 0; mt < MT; mt++) {
            const int row = wm * WM + mt * 16 + g;
            S[row * EST + col]           = c[mt][nt][0] + bb0;
            S[row * EST + col + 1]       = c[mt][nt][1] + bb1;
            S[(row + 8) * EST + col]     = c[mt][nt][2] + bb0;
            S[(row + 8) * EST + col + 1] = c[mt][nt][3] + bb1;
        }
    }
    if (FOLD && w < 2) {
        const int cl = w * 8 + tq * 2;
        const float bb0 = __ldg(&b0[cl]);
        const float bb1 = __ldg(&b0[cl + 1]);
#pragma unroll
        for (int mt = 0; mt < MT; mt++) {
            const int row = wm * WM + mt * 16 + g;
            S[row * EST + BN + cl]           = cx[mt][0] + bb0;
            S[row * EST + BN + cl + 1]       = cx[mt][1] + bb1;
            S[(row + 8) * EST + BN + cl]     = cx[mt][2] + bb0;
            S[(row + 8) * EST + BN + cl + 1] = cx[mt][3] + bb1;
        }
    }
    __syncthreads();

    // ---- level-0 lse + lp0 write (fold only) ----
    if (FOLD) {
        if (tid < BM) lse0v[tid] = lse16(S + tid * EST + BN);
        __syncthreads();
        if (blockIdx.x == 0 && tid < BM) {
            const float l0 = lse0v[tid];
            const float* p = S + tid * EST + BN;
            float* o = out + (size_t)(row0 + tid) * OW;
#pragma unroll
            for (int cc = 0; cc < 4; cc++) {
                float4 v;
                v.x = p[cc * 4 + 0] - l0; v.y = p[cc * 4 + 1] - l0;
                v.z = p[cc * 4 + 2] - l0; v.w = p[cc * 4 + 3] - l0;
                reinterpret_cast<float4*>(o)[cc] = v;
            }
        }
    }

    // ---- group-of-16 log-softmax (+parent chain), in place ----
    constexpr int GROUPS = BN / 16;
    for (int task = tid; task < BM * GROUPS; task += NTH) {
        const int rr = task / GROUPS;
        const int gg = task % GROUPS;
        float* p = S + rr * EST + gg * 16;
        const float lse = lse16(p);
        const int grow = row0 + rr;
        const int gc   = n0 + gg * 16;
        float pl;
        if (FOLD) {
            pl = S[rr * EST + BN + (gc >> 4)] - lse0v[rr];
        } else {
            pl = out[(size_t)grow * OW + 16 + (gc >> 4)];
        }
        const float adj = pl - lse;
#pragma unroll
        for (int j = 0; j < 16; j++) p[j] += adj;
    }
    __syncthreads();

    // ---- coalesced store-out ----
    constexpr int F4 = BN / 4;
    for (int idx = tid; idx < BM * F4; idx += NTH) {
        const int rr = idx / F4, c4 = idx % F4;
        float4 val = *reinterpret_cast<const float4*>(S + rr * EST + c4 * 4);
        const int gr = row0 + rr;
        const int gc = n0 + c4 * 4;
        if (LEVEL == 1)
            *reinterpret_cast<float4*>(out + (size_t)gr * OW + 16 + gc) = val;
        if (LEVEL == 2) {
            *reinterpret_cast<float4*>(out + (size_t)gr * OW + 272 + gc) = val;
            *reinterpret_cast<float4*>(out + (size_t)B * OW + (size_t)gr * 4096 + gc) = val;
        }
    }
}

} // namespace

extern "C" void kernel_launch(void* const* d_in, const int* in_sizes, int n_in,
                              void* d_out, int out_size)
{
    const float* x  = (const float*)d_in[0];
    const float* W0 = (const float*)d_in[1];
    const float* b0 = (const float*)d_in[2];
    const float* W1 = (const float*)d_in[3];
    const float* b1 = (const float*)d_in[4];
    const float* W2 = (const float*)d_in[5];
    const float* b2 = (const float*)d_in[6];
    float* out = (float*)d_out;
    const int B = in_sizes[0] / D_;   // 4096

    __half *xh, *w2h, *w1h;
    cudaGetSymbolAddress((void**)&xh,  g_xh);
    cudaGetSymbolAddress((void**)&w2h, g_w2h);
    cudaGetSymbolAddress((void**)&w1h, g_w1h);

    cvt_all<<<2048, 256>>>(x, W2, W1, W0, B);

    // K1: BM=32, BN=128 (+16 folded W0 rows), 4 warps, NS=3
    constexpr int SM_K1  = 3 * (32 * 128 + 144 * 128);
    constexpr int EPI_K1 = 32 * (144 + 4) * 4;
    constexpr int DYN_K1 = (SM_K1 > EPI_K1) ? SM_K1 : EPI_K1;
    // K2: BM=128, BN=128, 4 warps (warp tile 64x64), NS=3, 2 CTAs/SM
    constexpr int SM_K2  = 3 * (128 * 128 + 128 * 128);    // 98304
    constexpr int EPI_K2 = 128 * (128 + 4) * 4;            // 67584
    constexpr int DYN_K2 = (SM_K2 > EPI_K2) ? SM_K2 : EPI_K2;

    cudaFuncSetAttribute((const void*)hs_mma<32, 128, 144, 128, 1, 4, 3, 2, 1>,
                         cudaFuncAttributeMaxDynamicSharedMemorySize, DYN_K1);
    cudaFuncSetAttribute((const void*)hs_mma<128, 128, 128, 128, 2, 2, 3, 2, 2>,
                         cudaFuncAttributeMaxDynamicSharedMemorySize, DYN_K2);

    hs_mma<32, 128, 144, 128, 1, 4, 3, 2, 1>
        <<<dim3(2, B / 32), 128, DYN_K1>>>(xh, w1h, b1, b0, out, B);
    hs_mma<128, 128, 128, 128, 2, 2, 3, 2, 2>
        <<<dim3(32, B / 128), 128, DYN_K2>>>(xh, w2h, b2, nullptr, out, B);
}